// round 15
// baseline (speedup 1.0000x reference)
#include <cuda_runtime.h>
#include <cuda_fp16.h>
#include <math.h>

// Problem dims (fixed by dataset)
#define N_NODES 50000
#define N_EDGES 500000
#define C_IN    256
#define H       128
#define H2      256
#define NLAYERS 4
#define NGRAPH  64
#define KCLIN   8
#define NCLS    2
#define EPS_MSG 1e-7f
#define EPS_BN  1e-5f

#define SCAN_B  512
#define SCAN_NB ((N_NODES + SCAN_B - 1) / SCAN_B)   // 98
#define SMS 136    // B smem row stride in words (mod 32 == 8 -> conflict-free)
#define ASTRIDE 20 // A stage row stride (20*r mod 32 distinct)
#define MIDSTRIDE 132 // mid row stride (4*r mod 32 distinct)
#define MTILES  ((N_NODES + 255) / 256)             // 196

// ---------------------------------------------------------------------------
// Scratch (device globals; no allocation allowed)
// ---------------------------------------------------------------------------
__device__ float    g_xsd [N_NODES * 256];   // layer-0 src|dst projections
__device__ float    g_xs  [N_NODES * H];     // r buffer (layers >= 1)
__device__ float    g_h   [N_NODES * H];
__device__ unsigned g_obuf[N_NODES * 64];    // gather out, packed fp16x2
__device__ unsigned g_xf  [N_NODES * 128];   // x packed fp16x2
__device__ float    g_pool[NGRAPH * H];
__device__ float    g_cnt [NGRAPH];

// fp16 weights (packed f16x2 pairs along K), N-major [k2][n]
__device__ unsigned g_B0[128 * 256];
__device__ float    g_bias0[256];
__device__ unsigned g_W1[NLAYERS * 64 * 256];
__device__ unsigned g_W2[NLAYERS * 128 * 128];

// CSR build scratch
__device__ int  g_count[N_NODES];
__device__ int  g_row  [N_NODES + 1];
__device__ int  g_bsum [128];
__device__ int2 g_edges[N_EDGES];

// ---------------------------------------------------------------------------
// helpers
// ---------------------------------------------------------------------------
__device__ __forceinline__ unsigned packhf(float lo, float hi) {
    unsigned r;  // low half = lo, high half = hi
    asm("cvt.rn.f16x2.f32 %0, %1, %2;" : "=r"(r) : "f"(hi), "f"(lo));
    return r;
}
__device__ __forceinline__ void mma_f16(float c[4],
                                        unsigned a0, unsigned a1, unsigned a2, unsigned a3,
                                        unsigned b0, unsigned b1) {
    asm volatile(
        "mma.sync.aligned.m16n8k16.row.col.f32.f16.f16.f32 "
        "{%0,%1,%2,%3}, {%4,%5,%6,%7}, {%8,%9}, {%0,%1,%2,%3};"
        : "+f"(c[0]), "+f"(c[1]), "+f"(c[2]), "+f"(c[3])
        : "r"(a0), "r"(a1), "r"(a2), "r"(a3), "r"(b0), "r"(b1));
}
__device__ __forceinline__ void cp_async16(void* smem, const void* gmem) {
    unsigned sa = (unsigned)__cvta_generic_to_shared(smem);
    asm volatile("cp.async.cg.shared.global [%0], [%1], 16;\n"
                 :: "r"(sa), "l"(gmem));
}
__device__ __forceinline__ void cp_async16p(void* smem, const void* gmem, bool pred) {
    unsigned sa = (unsigned)__cvta_generic_to_shared(smem);
    int sz = pred ? 16 : 0;
    asm volatile("cp.async.cg.shared.global [%0], [%1], 16, %2;\n"
                 :: "r"(sa), "l"(gmem), "r"(sz));
}
__device__ __forceinline__ void cp_commit() {
    asm volatile("cp.async.commit_group;\n" ::);
}
template<int W> __device__ __forceinline__ void cp_wait() {
    asm volatile("cp.async.wait_group %0;\n" :: "n"(W));
}

// ---------------------------------------------------------------------------
// pack_all: zero pool accumulators + convert all weights to fp16 (one launch)
// ---------------------------------------------------------------------------
__global__ void pack_all(const float* __restrict__ lsw, const float* __restrict__ ldw,
                         const float* __restrict__ lsb, const float* __restrict__ ldb,
                         const float* __restrict__ w1, const float* __restrict__ w2)
{
    int i = blockIdx.x * blockDim.x + threadIdx.x;
    int stride = gridDim.x * blockDim.x;
    if (i < NGRAPH * H) g_pool[i] = 0.f;
    if (i < NGRAPH) g_cnt[i] = 0.f;
    if (i < 256) g_bias0[i] = (i < 128) ? lsb[i] : ldb[i - 128];

    for (int idx = i; idx < 128 * 256; idx += stride) {
        int k2 = idx >> 8, n = idx & 255;
        float v0, v1;
        if (n < 128) { v0 = lsw[(2*k2)*128 + n];       v1 = lsw[(2*k2+1)*128 + n]; }
        else         { v0 = ldw[(2*k2)*128 + n - 128]; v1 = ldw[(2*k2+1)*128 + n - 128]; }
        g_B0[idx] = packhf(v0, v1);
    }
    for (int idx = i; idx < NLAYERS * 64 * 256; idx += stride) {
        int l = idx >> 14, rem = idx & 16383;
        int k2 = rem >> 8, n = rem & 255;
        const float* base = w1 + (long)l * 128 * 256;
        g_W1[idx] = packhf(base[(2*k2)*256 + n], base[(2*k2+1)*256 + n]);
    }
    for (int idx = i; idx < NLAYERS * 128 * 128; idx += stride) {
        int l = idx >> 14, rem = idx & 16383;
        int k2 = rem >> 7, n = rem & 127;
        const float* base = w2 + (long)l * 256 * 128;
        g_W2[idx] = packhf(base[(2*k2)*128 + n], base[(2*k2+1)*128 + n]);
    }
}

// pack_x: node features -> packed fp16x2
__global__ void pack_x(const float* __restrict__ x) {
    int idx = blockIdx.x * blockDim.x + threadIdx.x;
    if (idx >= N_NODES * 128) return;
    int row = idx >> 7, k2 = idx & 127;
    float2 v = *reinterpret_cast<const float2*>(x + (long)row * 256 + 2 * k2);
    g_xf[idx] = packhf(v.x, v.y);
}

// ---------------------------------------------------------------------------
// CSR build (side stream)
// ---------------------------------------------------------------------------
__global__ void zero_counts() {
    int i = blockIdx.x * blockDim.x + threadIdx.x;
    if (i < N_NODES) g_count[i] = 0;
}

__global__ void hist_kernel(const int* __restrict__ dst) {
    int i = blockIdx.x * blockDim.x + threadIdx.x;
    if (i < N_EDGES) atomicAdd(&g_count[dst[i]], 1);
}

__global__ void scan_local_kernel() {
    __shared__ int sh[SCAN_B];
    int tid = threadIdx.x;
    int i = blockIdx.x * SCAN_B + tid;
    int v = (i < N_NODES) ? g_count[i] : 0;
    sh[tid] = v;
    __syncthreads();
    for (int off = 1; off < SCAN_B; off <<= 1) {
        int t = (tid >= off) ? sh[tid - off] : 0;
        __syncthreads();
        sh[tid] += t;
        __syncthreads();
    }
    if (i < N_NODES) g_row[i] = sh[tid] - v;
    if (tid == SCAN_B - 1) g_bsum[blockIdx.x] = sh[tid];
}

__global__ void scan_bsum_kernel() {
    __shared__ int sh[128];
    int tid = threadIdx.x;
    int v = (tid < SCAN_NB) ? g_bsum[tid] : 0;
    sh[tid] = v;
    __syncthreads();
    for (int off = 1; off < 128; off <<= 1) {
        int t = (tid >= off) ? sh[tid - off] : 0;
        __syncthreads();
        sh[tid] += t;
        __syncthreads();
    }
    if (tid < SCAN_NB) g_bsum[tid] = sh[tid] - v;
}

__global__ void scan_add_kernel() {
    int i = blockIdx.x * blockDim.x + threadIdx.x;
    if (i < N_NODES) {
        int r = g_row[i] + g_bsum[i / SCAN_B];
        g_row[i] = r;
        g_count[i] = r;
    }
    if (i == 0) g_row[N_NODES] = N_EDGES;
}

__global__ void scatter_kernel(const int* __restrict__ src,
                               const int* __restrict__ dst,
                               const float* __restrict__ eattr) {
    int e = blockIdx.x * blockDim.x + threadIdx.x;
    if (e >= N_EDGES) return;
    int d = dst[e];
    int pos = atomicAdd(&g_count[d], 1);
    g_edges[pos] = make_int2(src[e], __float_as_int(eattr[e]));
}

// ---------------------------------------------------------------------------
// Gather: one warp per dst node; softmax aggregation without max-shift.
// Writes packed fp16x2 for the following MLP.
// ---------------------------------------------------------------------------
__global__ __launch_bounds__(256)
void gather_kernel(const float* __restrict__ xs, int ldx,
                   const float* __restrict__ xd,
                   const float* __restrict__ ew,
                   const float* __restrict__ eb,
                   const float* __restrict__ tptr, int l)
{
    int warp = (blockIdx.x * blockDim.x + threadIdx.x) >> 5;
    if (warp >= N_NODES) return;
    int lane = threadIdx.x & 31;
    int c0 = lane * 4;

    float4 w4 = *reinterpret_cast<const float4*>(ew + c0);
    float4 b4 = *reinterpret_cast<const float4*>(eb + c0);
    float tv = tptr[l];

    int e0 = g_row[warp];
    int e1 = g_row[warp + 1];

    float n0 = 0.f, n1 = 0.f, n2 = 0.f, n3 = 0.f;
    float d0 = 0.f, d1 = 0.f, d2 = 0.f, d3 = 0.f;

#pragma unroll 4
    for (int e = e0; e < e1; e++) {
        int2 ed = g_edges[e];
        int   s  = ed.x;
        float al = __int_as_float(ed.y);
        float4 x4 = *reinterpret_cast<const float4*>(xs + (long)s * ldx + c0);

        float m0 = fmaxf(fmaf(al, w4.x, b4.x) + x4.x, 0.f) + EPS_MSG;
        float m1 = fmaxf(fmaf(al, w4.y, b4.y) + x4.y, 0.f) + EPS_MSG;
        float m2 = fmaxf(fmaf(al, w4.z, b4.z) + x4.z, 0.f) + EPS_MSG;
        float m3 = fmaxf(fmaf(al, w4.w, b4.w) + x4.w, 0.f) + EPS_MSG;

        float z0 = __expf(m0 * tv);
        float z1 = __expf(m1 * tv);
        float z2 = __expf(m2 * tv);
        float z3 = __expf(m3 * tv);

        d0 += z0; d1 += z1; d2 += z2; d3 += z3;
        n0 = fmaf(m0, z0, n0); n1 = fmaf(m1, z1, n1);
        n2 = fmaf(m2, z2, n2); n3 = fmaf(m3, z3, n3);
    }

    float4 xv = *reinterpret_cast<const float4*>(xd + (long)warp * ldx + c0);
    float ox = n0 / fmaxf(d0, 1e-16f) + xv.x;
    float oy = n1 / fmaxf(d1, 1e-16f) + xv.y;
    float oz = n2 / fmaxf(d2, 1e-16f) + xv.z;
    float ow = n3 / fmaxf(d3, 1e-16f) + xv.w;

    int p = warp * 64 + (c0 >> 1);
    *reinterpret_cast<uint2*>(g_obuf + p) =
        make_uint2(packhf(ox, oy), packhf(oz, ow));
}

// ---------------------------------------------------------------------------
// Input-projection GEMM: CTA tile 256x128, 256 threads (8 warps, 4x2),
// warp tile 64x64. Pure fp16 MMA. C = A@B + bias.
// ---------------------------------------------------------------------------
#define GEMM_SMEM ((2*256*ASTRIDE + 2*16*SMS) * 4)

__global__ __launch_bounds__(256)
void bgemm256(const unsigned* __restrict__ A_g,
              const unsigned* __restrict__ B_g,
              const float* __restrict__ bias, float* __restrict__ C,
              int M, int N, int K)
{
    extern __shared__ unsigned smem_[];
    unsigned* Aa = smem_;                      // [2][256][ASTRIDE]
    unsigned* Bb = Aa + 2 * 256 * ASTRIDE;     // [2][16][SMS]
#define AAS(s,r,k) Aa[((s)*256 + (r)) * ASTRIDE + (k)]
#define BBS(s,r,n) Bb[((s)*16 + (r)) * SMS + (n)]

    int tid = threadIdx.x;
    int wid = tid >> 5, lane = tid & 31;
    int tg = lane >> 2, tq = lane & 3;
    int warpM = wid >> 1, warpN = wid & 1;      // 4 x 2 warps
    int rowBase = blockIdx.x * 256;
    int colBase = blockIdx.y * 128;
    int mW = warpM * 64, nW = warpN * 64;
    int K2 = K >> 1;

    float acc[4][8][4];
#pragma unroll
    for (int mi = 0; mi < 4; mi++)
#pragma unroll
        for (int ni = 0; ni < 8; ni++)
#pragma unroll
            for (int r = 0; r < 4; r++) acc[mi][ni][r] = 0.f;

    auto load_stage = [&](int s, int k0) {
        int k20 = k0 >> 1;
#pragma unroll
        for (int i = 0; i < 4; i++) {
            int idx = tid + i * 256;
            int r = idx >> 2;
            int kc2 = (idx & 3) * 4;
            int gr = rowBase + r;
            bool ok = gr < M;
            long off = (long)(ok ? gr : 0) * K2 + k20 + kc2;
            cp_async16p(&AAS(s, r, kc2), A_g + off, ok);
        }
#pragma unroll
        for (int i = 0; i < 2; i++) {
            int idx = tid + i * 256;
            int kr = idx >> 5;
            int nc = (idx & 31) * 4;
            long off = (long)(k20 + kr) * N + colBase + nc;
            cp_async16(&BBS(s, kr, nc), B_g + off);
        }
        cp_commit();
    };

    int nIter = K >> 5;
    load_stage(0, 0);

    for (int it = 0; it < nIter; it++) {
        if (it + 1 < nIter) {
            load_stage((it + 1) & 1, (it + 1) << 5);
            cp_wait<1>();
        } else {
            cp_wait<0>();
        }
        __syncthreads();

        int s = it & 1;
#pragma unroll
        for (int kk = 0; kk < 2; kk++) {
            int k2a = kk * 8 + tq, k2b = k2a + 4;
            unsigned b0[8], b1[8];
#pragma unroll
            for (int ni = 0; ni < 8; ni++) {
                int n = nW + ni * 8 + tg;
                b0[ni] = BBS(s, k2a, n); b1[ni] = BBS(s, k2b, n);
            }
#pragma unroll
            for (int mi = 0; mi < 4; mi++) {
                int m = mW + mi * 16 + tg;
                unsigned a0 = AAS(s, m, k2a), a1 = AAS(s, m + 8, k2a);
                unsigned a2 = AAS(s, m, k2b), a3 = AAS(s, m + 8, k2b);
#pragma unroll
                for (int ni = 0; ni < 8; ni++)
                    mma_f16(acc[mi][ni], a0, a1, a2, a3, b0[ni], b1[ni]);
            }
        }
        __syncthreads();
    }

#pragma unroll
    for (int ni = 0; ni < 8; ni++) {
        int c = colBase + nW + ni * 8 + tq * 2;
        float2 bi = *reinterpret_cast<const float2*>(bias + c);
#pragma unroll
        for (int mi = 0; mi < 4; mi++) {
            int r0 = rowBase + mW + mi * 16 + tg;
#pragma unroll
            for (int half = 0; half < 2; half++) {
                int row = r0 + half * 8;
                if (row >= M) continue;
                float vL = acc[mi][ni][half * 2 + 0] + bi.x;
                float vH = acc[mi][ni][half * 2 + 1] + bi.y;
                *reinterpret_cast<float2*>(C + (long)row * N + c) = make_float2(vL, vH);
            }
        }
    }
#undef AAS
#undef BBS
}

// ---------------------------------------------------------------------------
// Fused MLP, 512 threads, 32x32 warp tiles, pure fp16 MMA.
//   mid = fp16(relu(bn(obuf @ W1 + b1)))   (mid resident in smem)
//   v   = mid @ W2 + b2
//   MODE 4: h  = v; R = relu(bn_next(h))
//   MODE 3: h += v; R = relu(bn_next(h))
//   MODE 2: h += v
// ---------------------------------------------------------------------------
#define FUSED_SMEM ((2*128*ASTRIDE + 2*16*SMS + 128*MIDSTRIDE) * 4)

template<int MODE>
__global__ __launch_bounds__(512)
void fused_mlp(const unsigned* __restrict__ A_g,
               const unsigned* __restrict__ W1_g,
               const unsigned* __restrict__ W2_g,
               const float* __restrict__ b1,
               const float* __restrict__ bnAg, const float* __restrict__ bnAb,
               const float* __restrict__ bnAm, const float* __restrict__ bnAv,
               const float* __restrict__ b2,
               float* __restrict__ C, float* __restrict__ R,
               const float* __restrict__ bnNg, const float* __restrict__ bnNb,
               const float* __restrict__ bnNm, const float* __restrict__ bnNv,
               int M)
{
    extern __shared__ unsigned smem_[];
    unsigned* Aa = smem_;                          // [2][128][ASTRIDE]
    unsigned* Bb = Aa + 2 * 128 * ASTRIDE;         // [2][16][SMS]
    unsigned* Mid = Bb + 2 * 16 * SMS;             // [128][MIDSTRIDE]
#define AAS(s,r,k) Aa[((s)*128 + (r)) * ASTRIDE + (k)]
#define BBS(s,r,n) Bb[((s)*16 + (r)) * SMS + (n)]
#define MIDS(r,k)  Mid[(r) * MIDSTRIDE + (k)]

    int tid = threadIdx.x;
    int wid = tid >> 5, lane = tid & 31;
    int tg = lane >> 2, tq = lane & 3;
    int warpM = wid >> 2, warpN = wid & 3;         // 4 x 4 warps
    int rowBase = blockIdx.x * 128;
    int mW = warpM * 32, nW = warpN * 32;

    float acc[2][4][4];

    // ---------------- Phase A: mid = fp16(relu(bn(obuf @ W1 + b1))) --------
    for (int halfN = 0; halfN < 2; halfN++) {
        int colBase = halfN * 128;
#pragma unroll
        for (int mi = 0; mi < 2; mi++)
#pragma unroll
            for (int ni = 0; ni < 4; ni++)
#pragma unroll
                for (int r = 0; r < 4; r++) acc[mi][ni][r] = 0.f;

        auto load_stageA = [&](int s, int k20) {
            {
                int r = tid >> 2;
                int kc2 = (tid & 3) * 4;
                int gr = rowBase + r;
                bool ok = gr < M;
                long off = (long)(ok ? gr : 0) * 64 + k20 + kc2;
                cp_async16p(&AAS(s, r, kc2), A_g + off, ok);
            }
            {
                int kr = tid >> 5;
                int nc = (tid & 31) * 4;
                long off = (long)(k20 + kr) * 256 + colBase + nc;
                cp_async16(&BBS(s, kr, nc), W1_g + off);
            }
            cp_commit();
        };

        load_stageA(0, 0);
        for (int it = 0; it < 4; it++) {
            if (it + 1 < 4) { load_stageA((it + 1) & 1, (it + 1) * 16); cp_wait<1>(); }
            else            { cp_wait<0>(); }
            __syncthreads();
            int s = it & 1;
#pragma unroll
            for (int kk = 0; kk < 2; kk++) {
                int k2a = kk * 8 + tq, k2b = k2a + 4;
                unsigned b0[4], b1v[4];
#pragma unroll
                for (int ni = 0; ni < 4; ni++) {
                    int n = nW + ni * 8 + tg;
                    b0[ni] = BBS(s, k2a, n); b1v[ni] = BBS(s, k2b, n);
                }
#pragma unroll
                for (int mi = 0; mi < 2; mi++) {
                    int m = mW + mi * 16 + tg;
                    unsigned a0 = AAS(s, m, k2a), a1 = AAS(s, m + 8, k2a);
                    unsigned a2 = AAS(s, m, k2b), a3 = AAS(s, m + 8, k2b);
#pragma unroll
                    for (int ni = 0; ni < 4; ni++)
                        mma_f16(acc[mi][ni], a0, a1, a2, a3, b0[ni], b1v[ni]);
                }
            }
            __syncthreads();
        }

        // epilogue -> mid smem (bn + relu, fp16x2)
#pragma unroll
        for (int ni = 0; ni < 4; ni++) {
            int c = colBase + nW + ni * 8 + tq * 2;
            float2 bi = *reinterpret_cast<const float2*>(b1 + c);
            float2 gg = *reinterpret_cast<const float2*>(bnAg + c);
            float2 gb = *reinterpret_cast<const float2*>(bnAb + c);
            float2 gm = *reinterpret_cast<const float2*>(bnAm + c);
            float2 gv = *reinterpret_cast<const float2*>(bnAv + c);
            float scL = gg.x * rsqrtf(gv.x + EPS_BN), shL = gb.x - gm.x * scL;
            float scH = gg.y * rsqrtf(gv.y + EPS_BN), shH = gb.y - gm.y * scH;
            int pcol = c >> 1;
#pragma unroll
            for (int mi = 0; mi < 2; mi++) {
#pragma unroll
                for (int hr = 0; hr < 2; hr++) {
                    int rl = mW + mi * 16 + tg + hr * 8;
                    float vL = acc[mi][ni][hr * 2 + 0] + bi.x;
                    float vH = acc[mi][ni][hr * 2 + 1] + bi.y;
                    float tL = fmaxf(fmaf(vL, scL, shL), 0.f);
                    float tH = fmaxf(fmaf(vH, scH, shH), 0.f);
                    MIDS(rl, pcol) = packhf(tL, tH);
                }
            }
        }
        __syncthreads();
    }

    // ---------------- Phase B: v = mid @ W2 + b2 ---------------------------
#pragma unroll
    for (int mi = 0; mi < 2; mi++)
#pragma unroll
        for (int ni = 0; ni < 4; ni++)
#pragma unroll
            for (int r = 0; r < 4; r++) acc[mi][ni][r] = 0.f;

    auto load_stageB = [&](int s, int k20) {
        int kr = tid >> 5;
        int nc = (tid & 31) * 4;
        long off = (long)(k20 + kr) * 128 + nc;
        cp_async16(&BBS(s, kr, nc), W2_g + off);
        cp_commit();
    };

    load_stageB(0, 0);
    for (int it = 0; it < 8; it++) {
        if (it + 1 < 8) { load_stageB((it + 1) & 1, (it + 1) * 16); cp_wait<1>(); }
        else            { cp_wait<0>(); }
        __syncthreads();
        int s = it & 1;
#pragma unroll
        for (int kk = 0; kk < 2; kk++) {
            int k2a = kk * 8 + tq, k2b = k2a + 4;
            int g2a = it * 16 + k2a, g2b = it * 16 + k2b;
            unsigned b0[4], b1v[4];
#pragma unroll
            for (int ni = 0; ni < 4; ni++) {
                int n = nW + ni * 8 + tg;
                b0[ni] = BBS(s, k2a, n); b1v[ni] = BBS(s, k2b, n);
            }
#pragma unroll
            for (int mi = 0; mi < 2; mi++) {
                int m = mW + mi * 16 + tg;
                unsigned a0 = MIDS(m, g2a), a1 = MIDS(m + 8, g2a);
                unsigned a2 = MIDS(m, g2b), a3 = MIDS(m + 8, g2b);
#pragma unroll
                for (int ni = 0; ni < 4; ni++)
                    mma_f16(acc[mi][ni], a0, a1, a2, a3, b0[ni], b1v[ni]);
            }
        }
        __syncthreads();
    }

    // Final epilogue
#pragma unroll
    for (int ni = 0; ni < 4; ni++) {
        int c = nW + ni * 8 + tq * 2;
        float2 bi = *reinterpret_cast<const float2*>(b2 + c);
        float scL = 1.f, shL = 0.f, scH = 1.f, shH = 0.f;
        if (MODE == 3 || MODE == 4) {
            float2 gg = *reinterpret_cast<const float2*>(bnNg + c);
            float2 gb = *reinterpret_cast<const float2*>(bnNb + c);
            float2 gm = *reinterpret_cast<const float2*>(bnNm + c);
            float2 gv = *reinterpret_cast<const float2*>(bnNv + c);
            scL = gg.x * rsqrtf(gv.x + EPS_BN); shL = gb.x - gm.x * scL;
            scH = gg.y * rsqrtf(gv.y + EPS_BN); shH = gb.y - gm.y * scH;
        }
#pragma unroll
        for (int mi = 0; mi < 2; mi++) {
            int r0 = rowBase + mW + mi * 16 + tg;
#pragma unroll
            for (int hr = 0; hr < 2; hr++) {
                int row = r0 + hr * 8;
                if (row >= M) continue;
                float vL = acc[mi][ni][hr * 2 + 0] + bi.x;
                float vH = acc[mi][ni][hr * 2 + 1] + bi.y;
                float2* p = reinterpret_cast<float2*>(C + (long)row * 128 + c);
                if (MODE == 4) {
                    *p = make_float2(vL, vH);
                    *reinterpret_cast<float2*>(R + (long)row * 128 + c) = make_float2(
                        fmaxf(fmaf(vL, scL, shL), 0.f), fmaxf(fmaf(vH, scH, shH), 0.f));
                } else if (MODE == 3) {
                    float2 old = *p;
                    float hL = old.x + vL, hH = old.y + vH;
                    *p = make_float2(hL, hH);
                    *reinterpret_cast<float2*>(R + (long)row * 128 + c) = make_float2(
                        fmaxf(fmaf(hL, scL, shL), 0.f), fmaxf(fmaf(hH, scH, shH), 0.f));
                } else { // MODE 2
                    float2 old = *p;
                    *p = make_float2(old.x + vL, old.y + vH);
                }
            }
        }
    }
#undef AAS
#undef BBS
#undef MIDS
}

// ---------------------------------------------------------------------------
#define POOL_CHUNK 64
__global__ void pool_kernel(const int* __restrict__ batch,
                            const float* __restrict__ gg,
                            const float* __restrict__ gb,
                            const float* __restrict__ gm,
                            const float* __restrict__ gv)
{
    int c = threadIdx.x;
    int n0 = blockIdx.x * POOL_CHUNK;
    int n1 = min(n0 + POOL_CHUNK, N_NODES);
    float sc = gg[c] * rsqrtf(gv[c] + EPS_BN);
    float sh = gb[c] - gm[c] * sc;

    int curg = batch[n0];
    float acc = 0.f, cnt = 0.f;
    for (int n = n0; n < n1; n++) {
        int bg = batch[n];
        float val = fmaxf(fmaf(g_h[(long)n * H + c], sc, sh), 0.f);
        if (bg != curg) {
            atomicAdd(&g_pool[curg * H + c], acc);
            if (c == 0) atomicAdd(&g_cnt[curg], cnt);
            acc = 0.f; cnt = 0.f; curg = bg;
        }
        acc += val; cnt += 1.f;
    }
    atomicAdd(&g_pool[curg * H + c], acc);
    if (c == 0) atomicAdd(&g_cnt[curg], cnt);
}

__global__ void cls_kernel(const float* __restrict__ clinical,
                           const float* __restrict__ cw,
                           const float* __restrict__ cb,
                           float* __restrict__ out)
{
    int tid = threadIdx.x;
    if (tid >= NGRAPH * NCLS) return;
    int g = tid >> 1;
    int c = tid & 1;
    float inv = 1.f / fmaxf(g_cnt[g], 1.f);
    float acc = cb[c];
    for (int j = 0; j < H; j++)
        acc += g_pool[g * H + j] * inv * cw[j * NCLS + c];
    for (int k = 0; k < KCLIN; k++)
        acc += clinical[g * KCLIN + k] * cw[(H + k) * NCLS + c];
    out[g * NCLS + c] = acc;
}

// ---------------------------------------------------------------------------
extern "C" void kernel_launch(void* const* d_in, const int* in_sizes, int n_in,
                              void* d_out, int out_size)
{
    const float* x        = (const float*)d_in[0];
    const int*   ei       = (const int*)  d_in[1];
    const float* eattr    = (const float*)d_in[2];
    const int*   batch    = (const int*)  d_in[3];
    const float* clinical = (const float*)d_in[4];
    const float* lsw = (const float*)d_in[5],  *lsb = (const float*)d_in[6];
    const float* ldw = (const float*)d_in[7],  *ldb = (const float*)d_in[8];
    const float* ew  = (const float*)d_in[9],  *ebp = (const float*)d_in[10];
    const float* t   = (const float*)d_in[11];
    const float* w1  = (const float*)d_in[12], *b1  = (const float*)d_in[13];
    const float* bg  = (const float*)d_in[14], *bb  = (const float*)d_in[15];
    const float* bm  = (const float*)d_in[16], *bv  = (const float*)d_in[17];
    const float* w2  = (const float*)d_in[18], *b2  = (const float*)d_in[19];
    const float* ng  = (const float*)d_in[20], *nb  = (const float*)d_in[21];
    const float* nm  = (const float*)d_in[22], *nv  = (const float*)d_in[23];
    const float* cw  = (const float*)d_in[24], *cb  = (const float*)d_in[25];
    float* out = (float*)d_out;

    const int* src = ei;
    const int* dstp = ei + N_EDGES;

    float *xsd, *xsr, *hbuf, *bias0;
    unsigned *obf, *xf, *B0, *W1, *W2;
    cudaGetSymbolAddress((void**)&xsd,  g_xsd);
    cudaGetSymbolAddress((void**)&xsr,  g_xs);
    cudaGetSymbolAddress((void**)&hbuf, g_h);
    cudaGetSymbolAddress((void**)&obf,  g_obuf);
    cudaGetSymbolAddress((void**)&xf,   g_xf);
    cudaGetSymbolAddress((void**)&B0,   g_B0);
    cudaGetSymbolAddress((void**)&W1,   g_W1);
    cudaGetSymbolAddress((void**)&W2,   g_W2);
    cudaGetSymbolAddress((void**)&bias0, g_bias0);

    static bool init_done = false;
    static cudaStream_t s2;
    static cudaEvent_t e0, e2;
    if (!init_done) {
        cudaFuncSetAttribute(bgemm256,     cudaFuncAttributeMaxDynamicSharedMemorySize, GEMM_SMEM);
        cudaFuncSetAttribute(fused_mlp<2>, cudaFuncAttributeMaxDynamicSharedMemorySize, FUSED_SMEM);
        cudaFuncSetAttribute(fused_mlp<3>, cudaFuncAttributeMaxDynamicSharedMemorySize, FUSED_SMEM);
        cudaFuncSetAttribute(fused_mlp<4>, cudaFuncAttributeMaxDynamicSharedMemorySize, FUSED_SMEM);
        cudaStreamCreateWithFlags(&s2, cudaStreamNonBlocking);
        cudaEventCreateWithFlags(&e0, cudaEventDisableTiming);
        cudaEventCreateWithFlags(&e2, cudaEventDisableTiming);
        init_done = true;
    }

    dim3 grid1((N_NODES + 127) / 128, 1);
    dim3 gridP(MTILES, 2);

    // Main stream: pack + projection GEMM
    pack_all<<<512, 256>>>(lsw, ldw, lsb, ldb, w1, w2);           // #1
    pack_x<<<(N_NODES * 128 + 255) / 256, 256>>>(x);              // #2

    // Fork side stream for the CSR chain
    cudaEventRecord(e0, 0);
    cudaStreamWaitEvent(s2, e0, 0);
    zero_counts<<<(N_NODES + 255) / 256, 256, 0, s2>>>();         // #3

    // Launch #4 (profiled): input projection GEMM (main stream)
    bgemm256<<<gridP, 256, GEMM_SMEM>>>(xf, B0, bias0, xsd,
                                        N_NODES, 256, 256);

    hist_kernel<<<(N_EDGES + 255) / 256, 256, 0, s2>>>(dstp);
    scan_local_kernel<<<SCAN_NB, SCAN_B, 0, s2>>>();
    scan_bsum_kernel<<<1, 128, 0, s2>>>();
    scan_add_kernel<<<(N_NODES + 255) / 256, 256, 0, s2>>>();
    scatter_kernel<<<(N_EDGES + 255) / 256, 256, 0, s2>>>(src, dstp, eattr);
    cudaEventRecord(e2, s2);
    cudaStreamWaitEvent(0, e2, 0);   // join before layers

    for (int l = 0; l < NLAYERS; l++) {
        if (l == 0)
            gather_kernel<<<(N_NODES * 32 + 255) / 256, 256>>>(
                xsd, 256, xsd + 128, ew + l * H, ebp + l * H, t, l);
        else
            gather_kernel<<<(N_NODES * 32 + 255) / 256, 256>>>(
                xsr, 128, xsr, ew + l * H, ebp + l * H, t, l);

        if (l == 0)
            fused_mlp<4><<<grid1, 512, FUSED_SMEM>>>(
                obf, W1 + l * 16384, W2 + l * 16384,
                b1 + l * H2, bg + l * H2, bb + l * H2, bm + l * H2, bv + l * H2,
                b2 + l * H, hbuf, xsr,
                ng + (l + 1) * H, nb + (l + 1) * H, nm + (l + 1) * H, nv + (l + 1) * H,
                N_NODES);
        else if (l < NLAYERS - 1)
            fused_mlp<3><<<grid1, 512, FUSED_SMEM>>>(
                obf, W1 + l * 16384, W2 + l * 16384,
                b1 + l * H2, bg + l * H2, bb + l * H2, bm + l * H2, bv + l * H2,
                b2 + l * H, hbuf, xsr,
                ng + (l + 1) * H, nb + (l + 1) * H, nm + (l + 1) * H, nv + (l + 1) * H,
                N_NODES);
        else
            fused_mlp<2><<<grid1, 512, FUSED_SMEM>>>(
                obf, W1 + l * 16384, W2 + l * 16384,
                b1 + l * H2, bg + l * H2, bb + l * H2, bm + l * H2, bv + l * H2,
                b2 + l * H, hbuf, nullptr,
                nullptr, nullptr, nullptr, nullptr,
                N_NODES);
    }

    pool_kernel<<<(N_NODES + POOL_CHUNK - 1) / POOL_CHUNK, H>>>(batch, ng, nb, nm, nv);
    cls_kernel<<<1, 128>>>(clinical, cw, cb, out);
}

// round 16
// speedup vs baseline: 1.2877x; 1.2877x over previous
#include <cuda_runtime.h>
#include <cuda_fp16.h>
#include <math.h>

// Problem dims (fixed by dataset)
#define N_NODES 50000
#define N_EDGES 500000
#define C_IN    256
#define H       128
#define H2      256
#define NLAYERS 4
#define NGRAPH  64
#define KCLIN   8
#define NCLS    2
#define EPS_MSG 1e-7f
#define EPS_BN  1e-5f

#define SCAN_B  512
#define SCAN_NB ((N_NODES + SCAN_B - 1) / SCAN_B)   // 98
#define SMS 136    // B smem row stride in words (mod 32 == 8 -> conflict-free)
#define ASTRIDE 20 // A stage row stride (20*r mod 32 distinct)
#define MIDSTRIDE 132 // mid row stride (4*r mod 32 distinct)
#define MTILES  ((N_NODES + 255) / 256)             // 196

// ---------------------------------------------------------------------------
// Scratch (device globals; no allocation allowed)
// ---------------------------------------------------------------------------
__device__ unsigned g_xsdh[N_NODES * 128];   // layer-0 projections, packed fp16x2
__device__ unsigned g_rbuf[N_NODES * 64];    // r buffer (layers >= 1), packed fp16x2
__device__ float    g_h   [N_NODES * H];
__device__ unsigned g_obuf[N_NODES * 64];    // gather out, packed fp16x2
__device__ unsigned g_xf  [N_NODES * 128];   // x packed fp16x2 (GEMM A operand)
__device__ float    g_pool[NGRAPH * H];
__device__ float    g_cnt [NGRAPH];

// Weights: A-side fp16 single; B-side fp16 hi/lo 2-term. N-major [k2][n].
__device__ unsigned g_B0h[128 * 256], g_B0l[128 * 256];
__device__ float    g_bias0[256];
__device__ unsigned g_W1h[NLAYERS * 64 * 256], g_W1l[NLAYERS * 64 * 256];
__device__ unsigned g_W2h[NLAYERS * 128 * 128], g_W2l[NLAYERS * 128 * 128];

// CSR build scratch
__device__ int  g_count[N_NODES];
__device__ int  g_row  [N_NODES + 1];
__device__ int  g_bsum [128];
__device__ int2 g_edges[N_EDGES];

// ---------------------------------------------------------------------------
// helpers
// ---------------------------------------------------------------------------
__device__ __forceinline__ unsigned packhf(float lo, float hi) {
    unsigned r;  // low half = lo, high half = hi
    asm("cvt.rn.f16x2.f32 %0, %1, %2;" : "=r"(r) : "f"(hi), "f"(lo));
    return r;
}
__device__ __forceinline__ void splitw2(float a, float b, unsigned& h, unsigned& l) {
    h = packhf(a, b);
    __half2 hh = *reinterpret_cast<__half2*>(&h);
    float ra = a - __half2float(__low2half(hh));
    float rb = b - __half2float(__high2half(hh));
    l = packhf(ra, rb);
}
__device__ __forceinline__ float2 up2(unsigned p) {
    return __half22float2(*reinterpret_cast<__half2*>(&p));
}
__device__ __forceinline__ void mma_f16(float c[4],
                                        unsigned a0, unsigned a1, unsigned a2, unsigned a3,
                                        unsigned b0, unsigned b1) {
    asm volatile(
        "mma.sync.aligned.m16n8k16.row.col.f32.f16.f16.f32 "
        "{%0,%1,%2,%3}, {%4,%5,%6,%7}, {%8,%9}, {%0,%1,%2,%3};"
        : "+f"(c[0]), "+f"(c[1]), "+f"(c[2]), "+f"(c[3])
        : "r"(a0), "r"(a1), "r"(a2), "r"(a3), "r"(b0), "r"(b1));
}
__device__ __forceinline__ void cp_async16(void* smem, const void* gmem) {
    unsigned sa = (unsigned)__cvta_generic_to_shared(smem);
    asm volatile("cp.async.cg.shared.global [%0], [%1], 16;\n"
                 :: "r"(sa), "l"(gmem));
}
__device__ __forceinline__ void cp_async16p(void* smem, const void* gmem, bool pred) {
    unsigned sa = (unsigned)__cvta_generic_to_shared(smem);
    int sz = pred ? 16 : 0;
    asm volatile("cp.async.cg.shared.global [%0], [%1], 16, %2;\n"
                 :: "r"(sa), "l"(gmem), "r"(sz));
}
__device__ __forceinline__ void cp_commit() {
    asm volatile("cp.async.commit_group;\n" ::);
}
template<int W> __device__ __forceinline__ void cp_wait() {
    asm volatile("cp.async.wait_group %0;\n" :: "n"(W));
}

// ---------------------------------------------------------------------------
// pack_all: zero pool accumulators + pre-split all weights (one launch)
// ---------------------------------------------------------------------------
__global__ void pack_all(const float* __restrict__ lsw, const float* __restrict__ ldw,
                         const float* __restrict__ lsb, const float* __restrict__ ldb,
                         const float* __restrict__ w1, const float* __restrict__ w2)
{
    int i = blockIdx.x * blockDim.x + threadIdx.x;
    int stride = gridDim.x * blockDim.x;
    if (i < NGRAPH * H) g_pool[i] = 0.f;
    if (i < NGRAPH) g_cnt[i] = 0.f;
    if (i < 256) g_bias0[i] = (i < 128) ? lsb[i] : ldb[i - 128];

    for (int idx = i; idx < 128 * 256; idx += stride) {
        int k2 = idx >> 8, n = idx & 255;
        float v0, v1;
        if (n < 128) { v0 = lsw[(2*k2)*128 + n];       v1 = lsw[(2*k2+1)*128 + n]; }
        else         { v0 = ldw[(2*k2)*128 + n - 128]; v1 = ldw[(2*k2+1)*128 + n - 128]; }
        unsigned h, l; splitw2(v0, v1, h, l);
        g_B0h[idx] = h; g_B0l[idx] = l;
    }
    for (int idx = i; idx < NLAYERS * 64 * 256; idx += stride) {
        int l = idx >> 14, rem = idx & 16383;
        int k2 = rem >> 8, n = rem & 255;
        const float* base = w1 + (long)l * 128 * 256;
        unsigned h, lo; splitw2(base[(2*k2)*256 + n], base[(2*k2+1)*256 + n], h, lo);
        g_W1h[idx] = h; g_W1l[idx] = lo;
    }
    for (int idx = i; idx < NLAYERS * 128 * 128; idx += stride) {
        int l = idx >> 14, rem = idx & 16383;
        int k2 = rem >> 7, n = rem & 127;
        const float* base = w2 + (long)l * 256 * 128;
        unsigned h, lo; splitw2(base[(2*k2)*128 + n], base[(2*k2+1)*128 + n], h, lo);
        g_W2h[idx] = h; g_W2l[idx] = lo;
    }
}

// pack_x: node features -> packed fp16x2
__global__ void pack_x(const float* __restrict__ x) {
    int idx = blockIdx.x * blockDim.x + threadIdx.x;
    if (idx >= N_NODES * 128) return;
    int row = idx >> 7, k2 = idx & 127;
    float2 v = *reinterpret_cast<const float2*>(x + (long)row * 256 + 2 * k2);
    g_xf[idx] = packhf(v.x, v.y);
}

// ---------------------------------------------------------------------------
// CSR build (side stream)
// ---------------------------------------------------------------------------
__global__ void zero_counts() {
    int i = blockIdx.x * blockDim.x + threadIdx.x;
    if (i < N_NODES) g_count[i] = 0;
}

__global__ void hist_kernel(const int* __restrict__ dst) {
    int i = blockIdx.x * blockDim.x + threadIdx.x;
    if (i < N_EDGES) atomicAdd(&g_count[dst[i]], 1);
}

__global__ void scan_local_kernel() {
    __shared__ int sh[SCAN_B];
    int tid = threadIdx.x;
    int i = blockIdx.x * SCAN_B + tid;
    int v = (i < N_NODES) ? g_count[i] : 0;
    sh[tid] = v;
    __syncthreads();
    for (int off = 1; off < SCAN_B; off <<= 1) {
        int t = (tid >= off) ? sh[tid - off] : 0;
        __syncthreads();
        sh[tid] += t;
        __syncthreads();
    }
    if (i < N_NODES) g_row[i] = sh[tid] - v;
    if (tid == SCAN_B - 1) g_bsum[blockIdx.x] = sh[tid];
}

__global__ void scan_bsum_kernel() {
    __shared__ int sh[128];
    int tid = threadIdx.x;
    int v = (tid < SCAN_NB) ? g_bsum[tid] : 0;
    sh[tid] = v;
    __syncthreads();
    for (int off = 1; off < 128; off <<= 1) {
        int t = (tid >= off) ? sh[tid - off] : 0;
        __syncthreads();
        sh[tid] += t;
        __syncthreads();
    }
    if (tid < SCAN_NB) g_bsum[tid] = sh[tid] - v;
}

__global__ void scan_add_kernel() {
    int i = blockIdx.x * blockDim.x + threadIdx.x;
    if (i < N_NODES) {
        int r = g_row[i] + g_bsum[i / SCAN_B];
        g_row[i] = r;
        g_count[i] = r;
    }
    if (i == 0) g_row[N_NODES] = N_EDGES;
}

__global__ void scatter_kernel(const int* __restrict__ src,
                               const int* __restrict__ dst,
                               const float* __restrict__ eattr) {
    int e = blockIdx.x * blockDim.x + threadIdx.x;
    if (e >= N_EDGES) return;
    int d = dst[e];
    int pos = atomicAdd(&g_count[d], 1);
    g_edges[pos] = make_int2(src[e], __float_as_int(eattr[e]));
}

// ---------------------------------------------------------------------------
// Gather: one warp per dst node; softmax aggregation without max-shift.
// Inputs are packed fp16x2 rows (halved L2 traffic); output packed fp16x2.
// ---------------------------------------------------------------------------
__global__ __launch_bounds__(256)
void gather_kernel(const unsigned* __restrict__ xs, int ldx,
                   const unsigned* __restrict__ xd,
                   const float* __restrict__ ew,
                   const float* __restrict__ eb,
                   const float* __restrict__ tptr, int l)
{
    int warp = (blockIdx.x * blockDim.x + threadIdx.x) >> 5;
    if (warp >= N_NODES) return;
    int lane = threadIdx.x & 31;
    int c0 = lane * 4;
    int pc = lane * 2;

    float4 w4 = *reinterpret_cast<const float4*>(ew + c0);
    float4 b4 = *reinterpret_cast<const float4*>(eb + c0);
    float tv = tptr[l];

    int e0 = g_row[warp];
    int e1 = g_row[warp + 1];

    float n0 = 0.f, n1 = 0.f, n2 = 0.f, n3 = 0.f;
    float d0 = 0.f, d1 = 0.f, d2 = 0.f, d3 = 0.f;

#pragma unroll 4
    for (int e = e0; e < e1; e++) {
        int2 ed = g_edges[e];
        int   s  = ed.x;
        float al = __int_as_float(ed.y);
        uint2 xp = *reinterpret_cast<const uint2*>(xs + (long)s * ldx + pc);
        float2 xa = up2(xp.x);
        float2 xb = up2(xp.y);

        float m0 = fmaxf(fmaf(al, w4.x, b4.x) + xa.x, 0.f) + EPS_MSG;
        float m1 = fmaxf(fmaf(al, w4.y, b4.y) + xa.y, 0.f) + EPS_MSG;
        float m2 = fmaxf(fmaf(al, w4.z, b4.z) + xb.x, 0.f) + EPS_MSG;
        float m3 = fmaxf(fmaf(al, w4.w, b4.w) + xb.y, 0.f) + EPS_MSG;

        float z0 = __expf(m0 * tv);
        float z1 = __expf(m1 * tv);
        float z2 = __expf(m2 * tv);
        float z3 = __expf(m3 * tv);

        d0 += z0; d1 += z1; d2 += z2; d3 += z3;
        n0 = fmaf(m0, z0, n0); n1 = fmaf(m1, z1, n1);
        n2 = fmaf(m2, z2, n2); n3 = fmaf(m3, z3, n3);
    }

    uint2 dp = *reinterpret_cast<const uint2*>(xd + (long)warp * ldx + pc);
    float2 da = up2(dp.x);
    float2 db = up2(dp.y);
    float ox = n0 / fmaxf(d0, 1e-16f) + da.x;
    float oy = n1 / fmaxf(d1, 1e-16f) + da.y;
    float oz = n2 / fmaxf(d2, 1e-16f) + db.x;
    float ow = n3 / fmaxf(d3, 1e-16f) + db.y;

    int p = warp * 64 + pc;
    *reinterpret_cast<uint2*>(g_obuf + p) =
        make_uint2(packhf(ox, oy), packhf(oz, ow));
}

// ---------------------------------------------------------------------------
// Input-projection GEMM: CTA tile 256x128, 256 threads (8 warps, 4x2),
// warp tile 64x64. fp16 2-term (A fp16; B hi+lo). C packed fp16x2 + bias.
// ---------------------------------------------------------------------------
#define GEMM_SMEM ((2*256*ASTRIDE + 2*16*SMS*2) * 4)

__global__ __launch_bounds__(256)
void bgemm256(const unsigned* __restrict__ A_g,
              const unsigned* __restrict__ Bh_g, const unsigned* __restrict__ Bl_g,
              const float* __restrict__ bias, unsigned* __restrict__ C16,
              int M, int N, int K)
{
    extern __shared__ unsigned smem_[];
    unsigned* Aa = smem_;                      // [2][256][ASTRIDE]
    unsigned* Bh = Aa + 2 * 256 * ASTRIDE;     // [2][16][SMS]
    unsigned* Bl = Bh + 2 * 16 * SMS;
#define AAS(s,r,k) Aa[((s)*256 + (r)) * ASTRIDE + (k)]
#define BHS(s,r,n) Bh[((s)*16 + (r)) * SMS + (n)]
#define BLS(s,r,n) Bl[((s)*16 + (r)) * SMS + (n)]

    int tid = threadIdx.x;
    int wid = tid >> 5, lane = tid & 31;
    int tg = lane >> 2, tq = lane & 3;
    int warpM = wid >> 1, warpN = wid & 1;      // 4 x 2 warps
    int rowBase = blockIdx.x * 256;
    int colBase = blockIdx.y * 128;
    int mW = warpM * 64, nW = warpN * 64;
    int K2 = K >> 1;

    float acc[4][8][4];
#pragma unroll
    for (int mi = 0; mi < 4; mi++)
#pragma unroll
        for (int ni = 0; ni < 8; ni++)
#pragma unroll
            for (int r = 0; r < 4; r++) acc[mi][ni][r] = 0.f;

    auto load_stage = [&](int s, int k0) {
        int k20 = k0 >> 1;
#pragma unroll
        for (int i = 0; i < 4; i++) {
            int idx = tid + i * 256;
            int r = idx >> 2;
            int kc2 = (idx & 3) * 4;
            int gr = rowBase + r;
            bool ok = gr < M;
            long off = (long)(ok ? gr : 0) * K2 + k20 + kc2;
            cp_async16p(&AAS(s, r, kc2), A_g + off, ok);
        }
#pragma unroll
        for (int i = 0; i < 2; i++) {
            int idx = tid + i * 256;
            int kr = idx >> 5;
            int nc = (idx & 31) * 4;
            long off = (long)(k20 + kr) * N + colBase + nc;
            cp_async16(&BHS(s, kr, nc), Bh_g + off);
            cp_async16(&BLS(s, kr, nc), Bl_g + off);
        }
        cp_commit();
    };

    int nIter = K >> 5;
    load_stage(0, 0);

    for (int it = 0; it < nIter; it++) {
        if (it + 1 < nIter) {
            load_stage((it + 1) & 1, (it + 1) << 5);
            cp_wait<1>();
        } else {
            cp_wait<0>();
        }
        __syncthreads();

        int s = it & 1;
#pragma unroll
        for (int kk = 0; kk < 2; kk++) {
            int k2a = kk * 8 + tq, k2b = k2a + 4;
            unsigned bh0[8], bh1[8], bl0[8], bl1[8];
#pragma unroll
            for (int ni = 0; ni < 8; ni++) {
                int n = nW + ni * 8 + tg;
                bh0[ni] = BHS(s, k2a, n); bh1[ni] = BHS(s, k2b, n);
                bl0[ni] = BLS(s, k2a, n); bl1[ni] = BLS(s, k2b, n);
            }
#pragma unroll
            for (int mi = 0; mi < 4; mi++) {
                int m = mW + mi * 16 + tg;
                unsigned a0 = AAS(s, m, k2a), a1 = AAS(s, m + 8, k2a);
                unsigned a2 = AAS(s, m, k2b), a3 = AAS(s, m + 8, k2b);
#pragma unroll
                for (int ni = 0; ni < 8; ni++) {
                    mma_f16(acc[mi][ni], a0, a1, a2, a3, bh0[ni], bh1[ni]);
                    mma_f16(acc[mi][ni], a0, a1, a2, a3, bl0[ni], bl1[ni]);
                }
            }
        }
        __syncthreads();
    }

#pragma unroll
    for (int ni = 0; ni < 8; ni++) {
        int c = colBase + nW + ni * 8 + tq * 2;
        float2 bi = *reinterpret_cast<const float2*>(bias + c);
#pragma unroll
        for (int mi = 0; mi < 4; mi++) {
            int r0 = rowBase + mW + mi * 16 + tg;
#pragma unroll
            for (int half = 0; half < 2; half++) {
                int row = r0 + half * 8;
                if (row >= M) continue;
                float vL = acc[mi][ni][half * 2 + 0] + bi.x;
                float vH = acc[mi][ni][half * 2 + 1] + bi.y;
                C16[(long)row * (N >> 1) + (c >> 1)] = packhf(vL, vH);
            }
        }
    }
#undef AAS
#undef BHS
#undef BLS
}

// ---------------------------------------------------------------------------
// Fused MLP, 512 threads, 32x32 warp tiles, fp16 2-term.
//   mid = fp16(relu(bn(obuf @ W1 + b1)))   (mid resident in smem)
//   v   = mid @ W2 + b2
//   MODE 4: h  = v; R16 = fp16(relu(bn_next(h)))
//   MODE 3: h += v; R16 = fp16(relu(bn_next(h)))
//   MODE 2: h += v
// ---------------------------------------------------------------------------
#define FUSED_SMEM ((2*128*ASTRIDE + 2*16*SMS*2 + 128*MIDSTRIDE) * 4)

template<int MODE>
__global__ __launch_bounds__(512)
void fused_mlp(const unsigned* __restrict__ A_g,
               const unsigned* __restrict__ W1h_g, const unsigned* __restrict__ W1l_g,
               const unsigned* __restrict__ W2h_g, const unsigned* __restrict__ W2l_g,
               const float* __restrict__ b1,
               const float* __restrict__ bnAg, const float* __restrict__ bnAb,
               const float* __restrict__ bnAm, const float* __restrict__ bnAv,
               const float* __restrict__ b2,
               float* __restrict__ C, unsigned* __restrict__ R16,
               const float* __restrict__ bnNg, const float* __restrict__ bnNb,
               const float* __restrict__ bnNm, const float* __restrict__ bnNv,
               int M)
{
    extern __shared__ unsigned smem_[];
    unsigned* Aa = smem_;                          // [2][128][ASTRIDE]
    unsigned* Bh = Aa + 2 * 128 * ASTRIDE;         // [2][16][SMS]
    unsigned* Bl = Bh + 2 * 16 * SMS;
    unsigned* Mid = Bl + 2 * 16 * SMS;             // [128][MIDSTRIDE]
#define AAS(s,r,k) Aa[((s)*128 + (r)) * ASTRIDE + (k)]
#define BHS(s,r,n) Bh[((s)*16 + (r)) * SMS + (n)]
#define BLS(s,r,n) Bl[((s)*16 + (r)) * SMS + (n)]
#define MIDS(r,k)  Mid[(r) * MIDSTRIDE + (k)]

    int tid = threadIdx.x;
    int wid = tid >> 5, lane = tid & 31;
    int tg = lane >> 2, tq = lane & 3;
    int warpM = wid >> 2, warpN = wid & 3;         // 4 x 4 warps
    int rowBase = blockIdx.x * 128;
    int mW = warpM * 32, nW = warpN * 32;

    float acc[2][4][4];

    // ---------------- Phase A: mid = fp16(relu(bn(obuf @ W1 + b1))) --------
    for (int halfN = 0; halfN < 2; halfN++) {
        int colBase = halfN * 128;
#pragma unroll
        for (int mi = 0; mi < 2; mi++)
#pragma unroll
            for (int ni = 0; ni < 4; ni++)
#pragma unroll
                for (int r = 0; r < 4; r++) acc[mi][ni][r] = 0.f;

        auto load_stageA = [&](int s, int k20) {
            {
                int r = tid >> 2;
                int kc2 = (tid & 3) * 4;
                int gr = rowBase + r;
                bool ok = gr < M;
                long off = (long)(ok ? gr : 0) * 64 + k20 + kc2;
                cp_async16p(&AAS(s, r, kc2), A_g + off, ok);
            }
            {
                int kr = tid >> 5;
                int nc = (tid & 31) * 4;
                long off = (long)(k20 + kr) * 256 + colBase + nc;
                cp_async16(&BHS(s, kr, nc), W1h_g + off);
                cp_async16(&BLS(s, kr, nc), W1l_g + off);
            }
            cp_commit();
        };

        load_stageA(0, 0);
        for (int it = 0; it < 4; it++) {
            if (it + 1 < 4) { load_stageA((it + 1) & 1, (it + 1) * 16); cp_wait<1>(); }
            else            { cp_wait<0>(); }
            __syncthreads();
            int s = it & 1;
#pragma unroll
            for (int kk = 0; kk < 2; kk++) {
                int k2a = kk * 8 + tq, k2b = k2a + 4;
                unsigned bh0[4], bh1[4], bl0[4], bl1[4];
#pragma unroll
                for (int ni = 0; ni < 4; ni++) {
                    int n = nW + ni * 8 + tg;
                    bh0[ni] = BHS(s, k2a, n); bh1[ni] = BHS(s, k2b, n);
                    bl0[ni] = BLS(s, k2a, n); bl1[ni] = BLS(s, k2b, n);
                }
#pragma unroll
                for (int mi = 0; mi < 2; mi++) {
                    int m = mW + mi * 16 + tg;
                    unsigned a0 = AAS(s, m, k2a), a1 = AAS(s, m + 8, k2a);
                    unsigned a2 = AAS(s, m, k2b), a3 = AAS(s, m + 8, k2b);
#pragma unroll
                    for (int ni = 0; ni < 4; ni++) {
                        mma_f16(acc[mi][ni], a0, a1, a2, a3, bh0[ni], bh1[ni]);
                        mma_f16(acc[mi][ni], a0, a1, a2, a3, bl0[ni], bl1[ni]);
                    }
                }
            }
            __syncthreads();
        }

        // epilogue -> mid smem (bn + relu, fp16x2)
#pragma unroll
        for (int ni = 0; ni < 4; ni++) {
            int c = colBase + nW + ni * 8 + tq * 2;
            float2 bi = *reinterpret_cast<const float2*>(b1 + c);
            float2 gg = *reinterpret_cast<const float2*>(bnAg + c);
            float2 gb = *reinterpret_cast<const float2*>(bnAb + c);
            float2 gm = *reinterpret_cast<const float2*>(bnAm + c);
            float2 gv = *reinterpret_cast<const float2*>(bnAv + c);
            float scL = gg.x * rsqrtf(gv.x + EPS_BN), shL = gb.x - gm.x * scL;
            float scH = gg.y * rsqrtf(gv.y + EPS_BN), shH = gb.y - gm.y * scH;
            int pcol = c >> 1;
#pragma unroll
            for (int mi = 0; mi < 2; mi++) {
#pragma unroll
                for (int hr = 0; hr < 2; hr++) {
                    int rl = mW + mi * 16 + tg + hr * 8;
                    float vL = acc[mi][ni][hr * 2 + 0] + bi.x;
                    float vH = acc[mi][ni][hr * 2 + 1] + bi.y;
                    float tL = fmaxf(fmaf(vL, scL, shL), 0.f);
                    float tH = fmaxf(fmaf(vH, scH, shH), 0.f);
                    MIDS(rl, pcol) = packhf(tL, tH);
                }
            }
        }
        __syncthreads();
    }

    // ---------------- Phase B: v = mid @ W2 + b2 ---------------------------
#pragma unroll
    for (int mi = 0; mi < 2; mi++)
#pragma unroll
        for (int ni = 0; ni < 4; ni++)
#pragma unroll
            for (int r = 0; r < 4; r++) acc[mi][ni][r] = 0.f;

    auto load_stageB = [&](int s, int k20) {
        int kr = tid >> 5;
        int nc = (tid & 31) * 4;
        long off = (long)(k20 + kr) * 128 + nc;
        cp_async16(&BHS(s, kr, nc), W2h_g + off);
        cp_async16(&BLS(s, kr, nc), W2l_g + off);
        cp_commit();
    };

    load_stageB(0, 0);
    for (int it = 0; it < 8; it++) {
        if (it + 1 < 8) { load_stageB((it + 1) & 1, (it + 1) * 16); cp_wait<1>(); }
        else            { cp_wait<0>(); }
        __syncthreads();
        int s = it & 1;
#pragma unroll
        for (int kk = 0; kk < 2; kk++) {
            int k2a = kk * 8 + tq, k2b = k2a + 4;
            int g2a = it * 16 + k2a, g2b = it * 16 + k2b;
            unsigned bh0[4], bh1[4], bl0[4], bl1[4];
#pragma unroll
            for (int ni = 0; ni < 4; ni++) {
                int n = nW + ni * 8 + tg;
                bh0[ni] = BHS(s, k2a, n); bh1[ni] = BHS(s, k2b, n);
                bl0[ni] = BLS(s, k2a, n); bl1[ni] = BLS(s, k2b, n);
            }
#pragma unroll
            for (int mi = 0; mi < 2; mi++) {
                int m = mW + mi * 16 + tg;
                unsigned a0 = MIDS(m, g2a), a1 = MIDS(m + 8, g2a);
                unsigned a2 = MIDS(m, g2b), a3 = MIDS(m + 8, g2b);
#pragma unroll
                for (int ni = 0; ni < 4; ni++) {
                    mma_f16(acc[mi][ni], a0, a1, a2, a3, bh0[ni], bh1[ni]);
                    mma_f16(acc[mi][ni], a0, a1, a2, a3, bl0[ni], bl1[ni]);
                }
            }
        }
        __syncthreads();
    }

    // Final epilogue
#pragma unroll
    for (int ni = 0; ni < 4; ni++) {
        int c = nW + ni * 8 + tq * 2;
        float2 bi = *reinterpret_cast<const float2*>(b2 + c);
        float scL = 1.f, shL = 0.f, scH = 1.f, shH = 0.f;
        if (MODE == 3 || MODE == 4) {
            float2 gg = *reinterpret_cast<const float2*>(bnNg + c);
            float2 gb = *reinterpret_cast<const float2*>(bnNb + c);
            float2 gm = *reinterpret_cast<const float2*>(bnNm + c);
            float2 gv = *reinterpret_cast<const float2*>(bnNv + c);
            scL = gg.x * rsqrtf(gv.x + EPS_BN); shL = gb.x - gm.x * scL;
            scH = gg.y * rsqrtf(gv.y + EPS_BN); shH = gb.y - gm.y * scH;
        }
#pragma unroll
        for (int mi = 0; mi < 2; mi++) {
            int r0 = rowBase + mW + mi * 16 + tg;
#pragma unroll
            for (int hr = 0; hr < 2; hr++) {
                int row = r0 + hr * 8;
                if (row >= M) continue;
                float vL = acc[mi][ni][hr * 2 + 0] + bi.x;
                float vH = acc[mi][ni][hr * 2 + 1] + bi.y;
                float2* p = reinterpret_cast<float2*>(C + (long)row * 128 + c);
                if (MODE == 4) {
                    *p = make_float2(vL, vH);
                    R16[(long)row * 64 + (c >> 1)] = packhf(
                        fmaxf(fmaf(vL, scL, shL), 0.f), fmaxf(fmaf(vH, scH, shH), 0.f));
                } else if (MODE == 3) {
                    float2 old = *p;
                    float hL = old.x + vL, hH = old.y + vH;
                    *p = make_float2(hL, hH);
                    R16[(long)row * 64 + (c >> 1)] = packhf(
                        fmaxf(fmaf(hL, scL, shL), 0.f), fmaxf(fmaf(hH, scH, shH), 0.f));
                } else { // MODE 2
                    float2 old = *p;
                    *p = make_float2(old.x + vL, old.y + vH);
                }
            }
        }
    }
#undef AAS
#undef BHS
#undef BLS
#undef MIDS
}

// ---------------------------------------------------------------------------
#define POOL_CHUNK 64
__global__ void pool_kernel(const int* __restrict__ batch,
                            const float* __restrict__ gg,
                            const float* __restrict__ gb,
                            const float* __restrict__ gm,
                            const float* __restrict__ gv)
{
    int c = threadIdx.x;
    int n0 = blockIdx.x * POOL_CHUNK;
    int n1 = min(n0 + POOL_CHUNK, N_NODES);
    float sc = gg[c] * rsqrtf(gv[c] + EPS_BN);
    float sh = gb[c] - gm[c] * sc;

    int curg = batch[n0];
    float acc = 0.f, cnt = 0.f;
    for (int n = n0; n < n1; n++) {
        int bg = batch[n];
        float val = fmaxf(fmaf(g_h[(long)n * H + c], sc, sh), 0.f);
        if (bg != curg) {
            atomicAdd(&g_pool[curg * H + c], acc);
            if (c == 0) atomicAdd(&g_cnt[curg], cnt);
            acc = 0.f; cnt = 0.f; curg = bg;
        }
        acc += val; cnt += 1.f;
    }
    atomicAdd(&g_pool[curg * H + c], acc);
    if (c == 0) atomicAdd(&g_cnt[curg], cnt);
}

__global__ void cls_kernel(const float* __restrict__ clinical,
                           const float* __restrict__ cw,
                           const float* __restrict__ cb,
                           float* __restrict__ out)
{
    int tid = threadIdx.x;
    if (tid >= NGRAPH * NCLS) return;
    int g = tid >> 1;
    int c = tid & 1;
    float inv = 1.f / fmaxf(g_cnt[g], 1.f);
    float acc = cb[c];
    for (int j = 0; j < H; j++)
        acc += g_pool[g * H + j] * inv * cw[j * NCLS + c];
    for (int k = 0; k < KCLIN; k++)
        acc += clinical[g * KCLIN + k] * cw[(H + k) * NCLS + c];
    out[g * NCLS + c] = acc;
}

// ---------------------------------------------------------------------------
extern "C" void kernel_launch(void* const* d_in, const int* in_sizes, int n_in,
                              void* d_out, int out_size)
{
    const float* x        = (const float*)d_in[0];
    const int*   ei       = (const int*)  d_in[1];
    const float* eattr    = (const float*)d_in[2];
    const int*   batch    = (const int*)  d_in[3];
    const float* clinical = (const float*)d_in[4];
    const float* lsw = (const float*)d_in[5],  *lsb = (const float*)d_in[6];
    const float* ldw = (const float*)d_in[7],  *ldb = (const float*)d_in[8];
    const float* ew  = (const float*)d_in[9],  *ebp = (const float*)d_in[10];
    const float* t   = (const float*)d_in[11];
    const float* w1  = (const float*)d_in[12], *b1  = (const float*)d_in[13];
    const float* bg  = (const float*)d_in[14], *bb  = (const float*)d_in[15];
    const float* bm  = (const float*)d_in[16], *bv  = (const float*)d_in[17];
    const float* w2  = (const float*)d_in[18], *b2  = (const float*)d_in[19];
    const float* ng  = (const float*)d_in[20], *nb  = (const float*)d_in[21];
    const float* nm  = (const float*)d_in[22], *nv  = (const float*)d_in[23];
    const float* cw  = (const float*)d_in[24], *cb  = (const float*)d_in[25];
    float* out = (float*)d_out;

    const int* src = ei;
    const int* dstp = ei + N_EDGES;

    float *hbuf, *bias0;
    unsigned *xsdh, *rbuf, *obf, *xf, *B0h, *B0l, *W1h, *W1l, *W2h, *W2l;
    cudaGetSymbolAddress((void**)&xsdh, g_xsdh);
    cudaGetSymbolAddress((void**)&rbuf, g_rbuf);
    cudaGetSymbolAddress((void**)&hbuf, g_h);
    cudaGetSymbolAddress((void**)&obf,  g_obuf);
    cudaGetSymbolAddress((void**)&xf,   g_xf);
    cudaGetSymbolAddress((void**)&B0h,  g_B0h);
    cudaGetSymbolAddress((void**)&B0l,  g_B0l);
    cudaGetSymbolAddress((void**)&W1h,  g_W1h);
    cudaGetSymbolAddress((void**)&W1l,  g_W1l);
    cudaGetSymbolAddress((void**)&W2h,  g_W2h);
    cudaGetSymbolAddress((void**)&W2l,  g_W2l);
    cudaGetSymbolAddress((void**)&bias0, g_bias0);

    static bool init_done = false;
    static cudaStream_t s2;
    static cudaEvent_t e0, e2;
    if (!init_done) {
        cudaFuncSetAttribute(bgemm256,     cudaFuncAttributeMaxDynamicSharedMemorySize, GEMM_SMEM);
        cudaFuncSetAttribute(fused_mlp<2>, cudaFuncAttributeMaxDynamicSharedMemorySize, FUSED_SMEM);
        cudaFuncSetAttribute(fused_mlp<3>, cudaFuncAttributeMaxDynamicSharedMemorySize, FUSED_SMEM);
        cudaFuncSetAttribute(fused_mlp<4>, cudaFuncAttributeMaxDynamicSharedMemorySize, FUSED_SMEM);
        cudaStreamCreateWithFlags(&s2, cudaStreamNonBlocking);
        cudaEventCreateWithFlags(&e0, cudaEventDisableTiming);
        cudaEventCreateWithFlags(&e2, cudaEventDisableTiming);
        init_done = true;
    }

    dim3 grid1((N_NODES + 127) / 128, 1);
    dim3 gridP(MTILES, 2);

    // Main stream: pack + projection GEMM
    pack_all<<<512, 256>>>(lsw, ldw, lsb, ldb, w1, w2);           // #1
    pack_x<<<(N_NODES * 128 + 255) / 256, 256>>>(x);              // #2

    // Fork side stream for the CSR chain
    cudaEventRecord(e0, 0);
    cudaStreamWaitEvent(s2, e0, 0);
    zero_counts<<<(N_NODES + 255) / 256, 256, 0, s2>>>();         // #3

    // Launch #4 (profiled): input projection GEMM (main stream)
    bgemm256<<<gridP, 256, GEMM_SMEM>>>(xf, B0h, B0l, bias0, xsdh,
                                        N_NODES, 256, 256);

    hist_kernel<<<(N_EDGES + 255) / 256, 256, 0, s2>>>(dstp);
    scan_local_kernel<<<SCAN_NB, SCAN_B, 0, s2>>>();
    scan_bsum_kernel<<<1, 128, 0, s2>>>();
    scan_add_kernel<<<(N_NODES + 255) / 256, 256, 0, s2>>>();
    scatter_kernel<<<(N_EDGES + 255) / 256, 256, 0, s2>>>(src, dstp, eattr);
    cudaEventRecord(e2, s2);
    cudaStreamWaitEvent(0, e2, 0);   // join before layers

    for (int l = 0; l < NLAYERS; l++) {
        if (l == 0)
            gather_kernel<<<(N_NODES * 32 + 255) / 256, 256>>>(
                xsdh, 128, xsdh + 64, ew + l * H, ebp + l * H, t, l);
        else
            gather_kernel<<<(N_NODES * 32 + 255) / 256, 256>>>(
                rbuf, 64, rbuf, ew + l * H, ebp + l * H, t, l);

        if (l == 0)
            fused_mlp<4><<<grid1, 512, FUSED_SMEM>>>(
                obf, W1h + l * 16384, W1l + l * 16384,
                W2h + l * 16384, W2l + l * 16384,
                b1 + l * H2, bg + l * H2, bb + l * H2, bm + l * H2, bv + l * H2,
                b2 + l * H, hbuf, rbuf,
                ng + (l + 1) * H, nb + (l + 1) * H, nm + (l + 1) * H, nv + (l + 1) * H,
                N_NODES);
        else if (l < NLAYERS - 1)
            fused_mlp<3><<<grid1, 512, FUSED_SMEM>>>(
                obf, W1h + l * 16384, W1l + l * 16384,
                W2h + l * 16384, W2l + l * 16384,
                b1 + l * H2, bg + l * H2, bb + l * H2, bm + l * H2, bv + l * H2,
                b2 + l * H, hbuf, rbuf,
                ng + (l + 1) * H, nb + (l + 1) * H, nm + (l + 1) * H, nv + (l + 1) * H,
                N_NODES);
        else
            fused_mlp<2><<<grid1, 512, FUSED_SMEM>>>(
                obf, W1h + l * 16384, W1l + l * 16384,
                W2h + l * 16384, W2l + l * 16384,
                b1 + l * H2, bg + l * H2, bb + l * H2, bm + l * H2, bv + l * H2,
                b2 + l * H, hbuf, nullptr,
                nullptr, nullptr, nullptr, nullptr,
                N_NODES);
    }

    pool_kernel<<<(N_NODES + POOL_CHUNK - 1) / POOL_CHUNK, H>>>(batch, ng, nb, nm, nv);
    cls_kernel<<<1, 128>>>(clinical, cw, cb, out);
}